// round 9
// baseline (speedup 1.0000x reference)
#include <cuda_runtime.h>
#include <cuda_bf16.h>
#include <cstdint>

#define BATCH 4
#define SEQ   4096
#define CDIM  512
#define DDIM  64
#define MROWS (BATCH*SEQ)
#define NKB   32              // key blocks of 128 in skernel

// device scratch (no allocation allowed)
__device__ __nv_bfloat16 g_xb [(size_t)MROWS * CDIM];         // bf16 x
__device__ __nv_bfloat16 g_wfT[DDIM * CDIM];                  // Wf^T [n][k]
__device__ __nv_bfloat16 g_wgT[DDIM * CDIM];                  // Wg^T
__device__ __nv_bfloat16 g_whT[CDIM * CDIM];                  // Wh^T
__device__ __nv_bfloat16 g_fb [MROWS * DDIM];                 // f  [m][64]
__device__ __nv_bfloat16 g_gb [MROWS * DDIM];                 // g  [m][64]
__device__ __nv_bfloat16 g_hTb[(size_t)BATCH * CDIM * SEQ];   // h^T [b][c][n]
__device__ __nv_bfloat16 g_pb [(size_t)BATCH * SEQ * SEQ];    // P = exp(S)  128 MB
__device__ float         g_lpart[NKB * MROWS];                // partial row sums
__device__ float         g_l[MROWS];                          // row sums

typedef unsigned int u32;

__device__ __forceinline__ void cp16(void* dst, const void* src) {
    u32 s = (u32)__cvta_generic_to_shared(dst);
    asm volatile("cp.async.cg.shared.global [%0], [%1], 16;\n" :: "r"(s), "l"(src));
}
__device__ __forceinline__ void cp_commit() {
    asm volatile("cp.async.commit_group;\n");
}

__device__ __forceinline__ void mma16816(float* c, const u32* a, u32 b0, u32 b1) {
    asm volatile(
        "mma.sync.aligned.m16n8k16.row.col.f32.bf16.bf16.f32 "
        "{%0,%1,%2,%3}, {%4,%5,%6,%7}, {%8,%9}, {%0,%1,%2,%3};"
        : "+f"(c[0]), "+f"(c[1]), "+f"(c[2]), "+f"(c[3])
        : "r"(a[0]), "r"(a[1]), "r"(a[2]), "r"(a[3]), "r"(b0), "r"(b1));
}

// ---------------------------------------------------------------------------
// Cast kernels
// ---------------------------------------------------------------------------
__global__ void __launch_bounds__(256)
cast_x(const float* __restrict__ x, __nv_bfloat16* __restrict__ xb)
{
    const size_t i = (size_t)blockIdx.x * 256 + threadIdx.x;
    float4 v = ((const float4*)x)[i];
    __nv_bfloat162 a = __floats2bfloat162_rn(v.x, v.y);
    __nv_bfloat162 b = __floats2bfloat162_rn(v.z, v.w);
    *(__nv_bfloat162*)&xb[4 * i]     = a;
    *(__nv_bfloat162*)&xb[4 * i + 2] = b;
}

// all three weight transpose-casts in one launch
__global__ void __launch_bounds__(256)
cast_w3(const float* __restrict__ Wf, const float* __restrict__ Wg,
        const float* __restrict__ Wh)
{
    const int i = blockIdx.x * 256 + threadIdx.x;
    if (i < 32768) {                       // Wf^T
        int n = i >> 9, k = i & 511;
        g_wfT[i] = __float2bfloat16(Wf[k * DDIM + n]);
    } else if (i < 65536) {                // Wg^T
        int j = i - 32768;
        int n = j >> 9, k = j & 511;
        g_wgT[j] = __float2bfloat16(Wg[k * DDIM + n]);
    } else {                               // Wh^T
        int j = i - 65536;
        int n = j >> 9, k = j & 511;
        g_whT[j] = __float2bfloat16(Wh[k * CDIM + n]);
    }
}

// ---------------------------------------------------------------------------
// Generic bf16 GEMM mainloop: BM=128, BN=64, BK=64, 256 thr, 3-deep pipeline.
// ---------------------------------------------------------------------------
#define PSTR     72
#define P_A_T    18432                 // 128*72*2
#define P_B_T    9216                  // 64*72*2
#define BUF_SZ   (P_A_T + P_B_T)       // 27648
#define P_SMEM   (3 * BUF_SZ)          // 82944

extern __shared__ __align__(16) unsigned char psm[];

__device__ __forceinline__ void load_chunk(
    const __nv_bfloat16* A, const __nv_bfloat16* BT,
    size_t strA, size_t strB, int m0, int n0, int c, int buf, int t)
{
    __nv_bfloat16* sA = (__nv_bfloat16*)(psm + buf * BUF_SZ);
    __nv_bfloat16* sB = (__nv_bfloat16*)(psm + buf * BUF_SZ + P_A_T);
    #pragma unroll
    for (int r = 0; r < 4; r++) {
        int idx = t + 256 * r;
        int row = idx >> 3, ck = idx & 7;
        cp16(&sA[row * PSTR + ck * 8],
             A + (size_t)(m0 + row) * strA + c * 64 + ck * 8);
    }
    #pragma unroll
    for (int r = 0; r < 2; r++) {
        int idx = t + 256 * r;
        int row = idx >> 3, ck = idx & 7;
        cp16(&sB[row * PSTR + ck * 8],
             BT + (size_t)(n0 + row) * strB + c * 64 + ck * 8);
    }
    cp_commit();
}

template <int NCHUNK>
__device__ __forceinline__ void gemm_mainloop(
    const __nv_bfloat16* A, const __nv_bfloat16* BT,
    size_t strA, size_t strB,
    int m0, int n0, int t, int w, int gid, int tig, float o[8][4])
{
    #pragma unroll
    for (int nt = 0; nt < 8; nt++)
        #pragma unroll
        for (int j = 0; j < 4; j++) o[nt][j] = 0.f;

    load_chunk(A, BT, strA, strB, m0, n0, 0, 0, t);
    load_chunk(A, BT, strA, strB, m0, n0, 1, 1, t);
    load_chunk(A, BT, strA, strB, m0, n0, 2, 2, t);

    for (int c = 0; c < NCHUNK; ++c) {
        asm volatile("cp.async.wait_group 2;\n");
        __syncthreads();
        const int buf = c % 3;
        const __nv_bfloat16* sA = (const __nv_bfloat16*)(psm + buf * BUF_SZ);
        const __nv_bfloat16* sB = (const __nv_bfloat16*)(psm + buf * BUF_SZ + P_A_T);

        u32 fa[4][4];
        const __nv_bfloat16* frow = &sA[(w * 16 + gid) * PSTR];
        #pragma unroll
        for (int ks = 0; ks < 4; ks++) {
            fa[ks][0] = *(const u32*)&frow[ks * 16 + 2 * tig];
            fa[ks][1] = *(const u32*)&frow[8 * PSTR + ks * 16 + 2 * tig];
            fa[ks][2] = *(const u32*)&frow[ks * 16 + 2 * tig + 8];
            fa[ks][3] = *(const u32*)&frow[8 * PSTR + ks * 16 + 2 * tig + 8];
        }
        #pragma unroll
        for (int nt = 0; nt < 8; nt++) {
            const __nv_bfloat16* brow = &sB[(nt * 8 + gid) * PSTR + 2 * tig];
            #pragma unroll
            for (int ks = 0; ks < 4; ks++) {
                u32 b0 = *(const u32*)&brow[ks * 16];
                u32 b1 = *(const u32*)&brow[ks * 16 + 8];
                mma16816(o[nt], fa[ks], b0, b1);
            }
        }
        __syncthreads();
        if (c + 3 < NCHUNK) load_chunk(A, BT, strA, strB, m0, n0, c + 3, buf, t);
        else                cp_commit();
    }
}

// ---------------------------------------------------------------------------
// Projections
// ---------------------------------------------------------------------------
__global__ void __launch_bounds__(256)
proj_small(const __nv_bfloat16* __restrict__ A, const __nv_bfloat16* __restrict__ BT,
           const float* __restrict__ bias, __nv_bfloat16* __restrict__ out)
{
    const int m0 = blockIdx.x * 128;
    const int t = threadIdx.x, w = t >> 5, lane = t & 31;
    const int gid = lane >> 2, tig = lane & 3;

    float o[8][4];
    gemm_mainloop<8>(A, BT, CDIM, CDIM, m0, 0, t, w, gid, tig, o);

    const int r0 = m0 + w * 16 + gid;
    #pragma unroll
    for (int nt = 0; nt < 8; nt++) {
        const int cc = nt * 8 + 2 * tig;
        const float b0 = bias[cc], b1 = bias[cc + 1];
        __nv_bfloat162 v0 = __floats2bfloat162_rn(o[nt][0] + b0, o[nt][1] + b1);
        __nv_bfloat162 v1 = __floats2bfloat162_rn(o[nt][2] + b0, o[nt][3] + b1);
        *(__nv_bfloat162*)&out[(size_t)r0 * DDIM + cc]       = v0;
        *(__nv_bfloat162*)&out[(size_t)(r0 + 8) * DDIM + cc] = v1;
    }
}

#define TSTR 136
__global__ void __launch_bounds__(256)
proj_big(const __nv_bfloat16* __restrict__ A, const __nv_bfloat16* __restrict__ BT,
         const float* __restrict__ bias)
{
    const int m0 = blockIdx.x * 128;
    const int n0 = blockIdx.y * 64;
    const int t = threadIdx.x, w = t >> 5, lane = t & 31;
    const int gid = lane >> 2, tig = lane & 3;

    float o[8][4];
    gemm_mainloop<8>(A, BT, CDIM, CDIM, m0, n0, t, w, gid, tig, o);

    __nv_bfloat16* st = (__nv_bfloat16*)psm;
    __syncthreads();
    const int m = w * 16 + gid;
    #pragma unroll
    for (int nt = 0; nt < 8; nt++) {
        const int cc = nt * 8 + 2 * tig;
        const float b0 = bias[n0 + cc], b1 = bias[n0 + cc + 1];
        st[cc * TSTR + m]           = __float2bfloat16(o[nt][0] + b0);
        st[(cc + 1) * TSTR + m]     = __float2bfloat16(o[nt][1] + b1);
        st[cc * TSTR + m + 8]       = __float2bfloat16(o[nt][2] + b0);
        st[(cc + 1) * TSTR + m + 8] = __float2bfloat16(o[nt][3] + b1);
    }
    __syncthreads();

    const int b  = m0 >> 12;
    const int nb = m0 & 4095;
    #pragma unroll
    for (int r = 0; r < 4; r++) {
        int idx = t + 256 * r;
        int row = idx >> 4, seg = idx & 15;
        float4 v = *(const float4*)&st[row * TSTR + seg * 8];
        *(float4*)&g_hTb[((size_t)b * CDIM + n0 + row) * SEQ + nb + seg * 8] = v;
    }
}

// ---------------------------------------------------------------------------
// skernel: P[b][q][k] = exp(f_q . g_k), plus partial row sums.
// ---------------------------------------------------------------------------
__global__ void __launch_bounds__(256)
skernel()
{
    __shared__ __nv_bfloat16 sf[128 * PSTR];
    __shared__ __nv_bfloat16 sg[128 * PSTR];

    const int qb = blockIdx.x, kb = blockIdx.y, b = blockIdx.z;
    const int q0 = qb * 128, k0 = kb * 128;
    const int t = threadIdx.x, w = t >> 5, lane = t & 31;
    const int gid = lane >> 2, tig = lane & 3;

    const __nv_bfloat16* fptr = g_fb + (size_t)(b * SEQ + q0) * DDIM;
    const __nv_bfloat16* gptr = g_gb + (size_t)(b * SEQ + k0) * DDIM;
    #pragma unroll
    for (int r = 0; r < 4; r++) {
        int idx = t + 256 * r;
        int row = idx >> 3, ck = idx & 7;
        cp16(&sf[row * PSTR + ck * 8], fptr + (size_t)row * DDIM + ck * 8);
    }
    #pragma unroll
    for (int r = 0; r < 4; r++) {
        int idx = t + 256 * r;
        int row = idx >> 3, ck = idx & 7;
        cp16(&sg[row * PSTR + ck * 8], gptr + (size_t)row * DDIM + ck * 8);
    }
    cp_commit();
    asm volatile("cp.async.wait_group 0;\n");
    __syncthreads();

    u32 fa[4][4];
    {
        const __nv_bfloat16* frow = &sf[(w * 16 + gid) * PSTR];
        #pragma unroll
        for (int ks = 0; ks < 4; ks++) {
            fa[ks][0] = *(const u32*)&frow[ks * 16 + 2 * tig];
            fa[ks][1] = *(const u32*)&frow[8 * PSTR + ks * 16 + 2 * tig];
            fa[ks][2] = *(const u32*)&frow[ks * 16 + 2 * tig + 8];
            fa[ks][3] = *(const u32*)&frow[8 * PSTR + ks * 16 + 2 * tig + 8];
        }
    }

    float s[16][4];
    #pragma unroll
    for (int nt = 0; nt < 16; nt++)
        #pragma unroll
        for (int j = 0; j < 4; j++) s[nt][j] = 0.f;

    #pragma unroll
    for (int nt = 0; nt < 16; nt++) {
        const __nv_bfloat16* brow = &sg[(nt * 8 + gid) * PSTR + 2 * tig];
        #pragma unroll
        for (int ks = 0; ks < 4; ks++) {
            u32 b0 = *(const u32*)&brow[ks * 16];
            u32 b1 = *(const u32*)&brow[ks * 16 + 8];
            mma16816(s[nt], fa[ks], b0, b1);
        }
    }

    __nv_bfloat16* P = g_pb + (size_t)b * SEQ * SEQ;
    const int row0 = q0 + w * 16 + gid;
    const int row1 = row0 + 8;
    float sl0 = 0.f, sl1 = 0.f;
    #pragma unroll
    for (int nt = 0; nt < 16; nt++) {
        float p0 = __expf(s[nt][0]);
        float p1 = __expf(s[nt][1]);
        float p2 = __expf(s[nt][2]);
        float p3 = __expf(s[nt][3]);
        sl0 += p0 + p1;
        sl1 += p2 + p3;
        const int key = k0 + nt * 8 + 2 * tig;
        __nv_bfloat162 lo = __floats2bfloat162_rn(p0, p1);
        __nv_bfloat162 hi = __floats2bfloat162_rn(p2, p3);
        *(__nv_bfloat162*)&P[(size_t)row0 * SEQ + key] = lo;
        *(__nv_bfloat162*)&P[(size_t)row1 * SEQ + key] = hi;
    }
    sl0 += __shfl_xor_sync(0xffffffffu, sl0, 1);
    sl0 += __shfl_xor_sync(0xffffffffu, sl0, 2);
    sl1 += __shfl_xor_sync(0xffffffffu, sl1, 1);
    sl1 += __shfl_xor_sync(0xffffffffu, sl1, 2);
    if (tig == 0) {
        g_lpart[kb * MROWS + b * SEQ + row0] = sl0;
        g_lpart[kb * MROWS + b * SEQ + row1] = sl1;
    }
}

__global__ void __launch_bounds__(256)
reduce_l()
{
    const int m = blockIdx.x * 256 + threadIdx.x;
    float s = 0.f;
    #pragma unroll
    for (int kb = 0; kb < NKB; kb++) s += g_lpart[kb * MROWS + m];
    g_l[m] = s;
}

// ---------------------------------------------------------------------------
// pvkernel: out = x + (gamma/l[row]) * (P . h^T)
// ---------------------------------------------------------------------------
__global__ void __launch_bounds__(256)
pvkernel(const float* __restrict__ x, const float* __restrict__ gamma_p,
         float* __restrict__ out)
{
    const int n0 = blockIdx.x * 64;     // channel block (x-major for P L2 reuse)
    const int m0 = blockIdx.y * 128;    // global row block
    const int b  = m0 >> 12;
    const int t = threadIdx.x, w = t >> 5, lane = t & 31;
    const int gid = lane >> 2, tig = lane & 3;

    const __nv_bfloat16* Pq = g_pb + ((size_t)b * SEQ + (m0 & 4095)) * SEQ;
    const __nv_bfloat16* BT = g_hTb + (size_t)b * CDIM * SEQ;

    float o[8][4];
    gemm_mainloop<SEQ / 64>(Pq, BT, SEQ, SEQ, 0, n0, t, w, gid, tig, o);

    const float gamma = *gamma_p;
    const int r0 = m0 + w * 16 + gid;
    const int r1 = r0 + 8;
    const float sc0 = gamma / g_l[r0];
    const float sc1 = gamma / g_l[r1];
    #pragma unroll
    for (int nt = 0; nt < 8; nt++) {
        const int cc = n0 + nt * 8 + 2 * tig;
        float2 x0 = *(const float2*)&x[(size_t)r0 * CDIM + cc];
        float2 x1 = *(const float2*)&x[(size_t)r1 * CDIM + cc];
        float2 o0, o1;
        o0.x = fmaf(o[nt][0], sc0, x0.x);
        o0.y = fmaf(o[nt][1], sc0, x0.y);
        o1.x = fmaf(o[nt][2], sc1, x1.x);
        o1.y = fmaf(o[nt][3], sc1, x1.y);
        *(float2*)&out[(size_t)r0 * CDIM + cc] = o0;
        *(float2*)&out[(size_t)r1 * CDIM + cc] = o1;
    }
}

// ---------------------------------------------------------------------------
extern "C" void kernel_launch(void* const* d_in, const int* in_sizes, int n_in,
                              void* d_out, int out_size)
{
    const float* x     = (const float*)d_in[0];
    const float* Wf    = (const float*)d_in[1];
    const float* bf    = (const float*)d_in[2];
    const float* Wg    = (const float*)d_in[3];
    const float* bg    = (const float*)d_in[4];
    const float* Wh    = (const float*)d_in[5];
    const float* bh    = (const float*)d_in[6];
    const float* gamma = (const float*)d_in[7];
    float* out = (float*)d_out;

    __nv_bfloat16 *xb, *wfT, *wgT, *whT, *fb, *gb;
    cudaGetSymbolAddress((void**)&xb,  g_xb);
    cudaGetSymbolAddress((void**)&wfT, g_wfT);
    cudaGetSymbolAddress((void**)&wgT, g_wgT);
    cudaGetSymbolAddress((void**)&whT, g_whT);
    cudaGetSymbolAddress((void**)&fb,  g_fb);
    cudaGetSymbolAddress((void**)&gb,  g_gb);

    static cudaStream_t s1 = nullptr;
    static cudaEvent_t  e0 = nullptr, e1 = nullptr;
    if (!s1) {
        cudaStreamCreateWithFlags(&s1, cudaStreamNonBlocking);
        cudaEventCreateWithFlags(&e0, cudaEventDisableTiming);
        cudaEventCreateWithFlags(&e1, cudaEventDisableTiming);
        cudaFuncSetAttribute(proj_small,
                             cudaFuncAttributeMaxDynamicSharedMemorySize, P_SMEM);
        cudaFuncSetAttribute(proj_big,
                             cudaFuncAttributeMaxDynamicSharedMemorySize, P_SMEM);
        cudaFuncSetAttribute(pvkernel,
                             cudaFuncAttributeMaxDynamicSharedMemorySize, P_SMEM);
    }

    // default stream: casts, then fork
    cast_x <<<MROWS * CDIM / 4 / 256, 256>>>(x, xb);
    cast_w3<<<(65536 + CDIM * CDIM) / 256, 256>>>(Wf, Wg, Wh);
    cudaEventRecord(e0, 0);

    // side stream: f, g projections -> S/P/exp -> l reduction
    cudaStreamWaitEvent(s1, e0, 0);
    proj_small<<<dim3(MROWS / 128), 256, P_SMEM, s1>>>(xb, wfT, bf, fb);
    proj_small<<<dim3(MROWS / 128), 256, P_SMEM, s1>>>(xb, wgT, bg, gb);
    skernel   <<<dim3(SEQ / 128, SEQ / 128, BATCH), 256, 0, s1>>>();
    reduce_l  <<<MROWS / 256, 256, 0, s1>>>();
    cudaEventRecord(e1, s1);

    // default stream: h projection overlaps the side stream
    proj_big<<<dim3(MROWS / 128, CDIM / 64), 256, P_SMEM>>>(xb, whT, bh);

    // join, then PV
    cudaStreamWaitEvent(0, e1, 0);
    pvkernel<<<dim3(CDIM / 64, MROWS / 128), 256, P_SMEM>>>(x, gamma, out);
}

// round 10
// speedup vs baseline: 1.0485x; 1.0485x over previous
#include <cuda_runtime.h>
#include <cuda_bf16.h>
#include <cstdint>

#define BATCH 4
#define SEQ   4096
#define CDIM  512
#define DDIM  64
#define MROWS (BATCH*SEQ)
#define NKB   32              // key blocks of 128 in skernel

// device scratch (no allocation allowed)
__device__ __nv_bfloat16 g_xb  [(size_t)MROWS * CDIM];         // bf16 x
__device__ __nv_bfloat16 g_wfgT[128 * CDIM];                   // [Wf;Wg]^T [n][k]
__device__ __nv_bfloat16 g_whT [CDIM * CDIM];                  // Wh^T
__device__ __nv_bfloat16 g_fb  [MROWS * DDIM];                 // f  [m][64]
__device__ __nv_bfloat16 g_gb  [MROWS * DDIM];                 // g  [m][64]
__device__ __nv_bfloat16 g_hTb [(size_t)BATCH * CDIM * SEQ];   // h^T [b][c][n]
__device__ __nv_bfloat16 g_pb  [(size_t)BATCH * SEQ * SEQ];    // P = exp(S) 128 MB
__device__ float         g_lpart[NKB * MROWS];                 // partial row sums
__device__ float         g_l[MROWS];                           // row sums

typedef unsigned int u32;

__device__ __forceinline__ void cp16(void* dst, const void* src) {
    u32 s = (u32)__cvta_generic_to_shared(dst);
    asm volatile("cp.async.cg.shared.global [%0], [%1], 16;\n" :: "r"(s), "l"(src));
}
__device__ __forceinline__ void cp_commit() {
    asm volatile("cp.async.commit_group;\n");
}

__device__ __forceinline__ void mma16816(float* c, const u32* a, u32 b0, u32 b1) {
    asm volatile(
        "mma.sync.aligned.m16n8k16.row.col.f32.bf16.bf16.f32 "
        "{%0,%1,%2,%3}, {%4,%5,%6,%7}, {%8,%9}, {%0,%1,%2,%3};"
        : "+f"(c[0]), "+f"(c[1]), "+f"(c[2]), "+f"(c[3])
        : "r"(a[0]), "r"(a[1]), "r"(a[2]), "r"(a[3]), "r"(b0), "r"(b1));
}

// ---------------------------------------------------------------------------
// Cast kernels
// ---------------------------------------------------------------------------
__global__ void __launch_bounds__(256)
cast_x(const float* __restrict__ x, __nv_bfloat16* __restrict__ xb)
{
    const size_t i = (size_t)blockIdx.x * 256 + threadIdx.x;
    float4 v = ((const float4*)x)[i];
    __nv_bfloat162 a = __floats2bfloat162_rn(v.x, v.y);
    __nv_bfloat162 b = __floats2bfloat162_rn(v.z, v.w);
    *(__nv_bfloat162*)&xb[4 * i]     = a;
    *(__nv_bfloat162*)&xb[4 * i + 2] = b;
}

// weight transpose-casts: [Wf;Wg]^T combined + Wh^T
__global__ void __launch_bounds__(256)
cast_w3(const float* __restrict__ Wf, const float* __restrict__ Wg,
        const float* __restrict__ Wh)
{
    const int i = blockIdx.x * 256 + threadIdx.x;
    if (i < 65536) {                       // [Wf;Wg]^T : n 0..127
        int n = i >> 9, k = i & 511;
        float v = (n < 64) ? Wf[k * DDIM + n] : Wg[k * DDIM + (n - 64)];
        g_wfgT[i] = __float2bfloat16(v);
    } else {                               // Wh^T
        int j = i - 65536;
        int n = j >> 9, k = j & 511;
        g_whT[j] = __float2bfloat16(Wh[k * CDIM + n]);
    }
}

// ---------------------------------------------------------------------------
// Generic bf16 GEMM mainloop: BM=128, BN=NTILES*8, BK=64, 256 thr, 2-deep.
// ---------------------------------------------------------------------------
#define PSTR 72

extern __shared__ __align__(16) unsigned char psm[];

template <int NTILES>
__device__ __forceinline__ void load_chunk(
    const __nv_bfloat16* A, const __nv_bfloat16* BT,
    size_t strA, size_t strB, int m0, int n0, int c, int buf, int t)
{
    constexpr int A_T = 128 * PSTR * 2;
    constexpr int BUF = A_T + NTILES * 8 * PSTR * 2;
    __nv_bfloat16* sA = (__nv_bfloat16*)(psm + buf * BUF);
    __nv_bfloat16* sB = (__nv_bfloat16*)(psm + buf * BUF + A_T);
    #pragma unroll
    for (int r = 0; r < 4; r++) {
        int idx = t + 256 * r;
        int row = idx >> 3, ck = idx & 7;
        cp16(&sA[row * PSTR + ck * 8],
             A + (size_t)(m0 + row) * strA + c * 64 + ck * 8);
    }
    #pragma unroll
    for (int r = 0; r < NTILES / 4; r++) {
        int idx = t + 256 * r;
        int row = idx >> 3, ck = idx & 7;
        cp16(&sB[row * PSTR + ck * 8],
             BT + (size_t)(n0 + row) * strB + c * 64 + ck * 8);
    }
    cp_commit();
}

template <int NCHUNK, int NTILES>
__device__ __forceinline__ void gemm_mainloop(
    const __nv_bfloat16* A, const __nv_bfloat16* BT,
    size_t strA, size_t strB,
    int m0, int n0, int t, int w, int gid, int tig, float (*o)[4])
{
    constexpr int A_T = 128 * PSTR * 2;
    constexpr int BUF = A_T + NTILES * 8 * PSTR * 2;

    #pragma unroll
    for (int nt = 0; nt < NTILES; nt++)
        #pragma unroll
        for (int j = 0; j < 4; j++) o[nt][j] = 0.f;

    load_chunk<NTILES>(A, BT, strA, strB, m0, n0, 0, 0, t);
    load_chunk<NTILES>(A, BT, strA, strB, m0, n0, 1, 1, t);

    for (int c = 0; c < NCHUNK; ++c) {
        if (c + 2 < NCHUNK) asm volatile("cp.async.wait_group 1;\n");
        else                asm volatile("cp.async.wait_group 0;\n");
        __syncthreads();
        const int buf = c & 1;
        const __nv_bfloat16* sA = (const __nv_bfloat16*)(psm + buf * BUF);
        const __nv_bfloat16* sB = (const __nv_bfloat16*)(psm + buf * BUF + A_T);

        u32 fa[4][4];
        const __nv_bfloat16* frow = &sA[(w * 16 + gid) * PSTR];
        #pragma unroll
        for (int ks = 0; ks < 4; ks++) {
            fa[ks][0] = *(const u32*)&frow[ks * 16 + 2 * tig];
            fa[ks][1] = *(const u32*)&frow[8 * PSTR + ks * 16 + 2 * tig];
            fa[ks][2] = *(const u32*)&frow[ks * 16 + 2 * tig + 8];
            fa[ks][3] = *(const u32*)&frow[8 * PSTR + ks * 16 + 2 * tig + 8];
        }
        #pragma unroll
        for (int nt = 0; nt < NTILES; nt++) {
            const __nv_bfloat16* brow = &sB[(nt * 8 + gid) * PSTR + 2 * tig];
            #pragma unroll
            for (int ks = 0; ks < 4; ks++) {
                u32 b0 = *(const u32*)&brow[ks * 16];
                u32 b1 = *(const u32*)&brow[ks * 16 + 8];
                mma16816(o[nt], fa[ks], b0, b1);
            }
        }
        __syncthreads();
        if (c + 2 < NCHUNK) load_chunk<NTILES>(A, BT, strA, strB, m0, n0, c + 2, buf, t);
        else                cp_commit();
    }
}

#define SMEM_N8   ((128 * PSTR * 2 + 64 * PSTR * 2) * 2)    // 55296
#define SMEM_N16  ((128 * PSTR * 2 + 128 * PSTR * 2) * 2)   // 73728

// ---------------------------------------------------------------------------
// proj_fg: f and g in one BN=128 GEMM against [Wf;Wg]^T
// ---------------------------------------------------------------------------
__global__ void __launch_bounds__(256)
proj_fg(const __nv_bfloat16* __restrict__ A,
        const float* __restrict__ bf, const float* __restrict__ bg)
{
    const int m0 = blockIdx.x * 128;
    const int t = threadIdx.x, w = t >> 5, lane = t & 31;
    const int gid = lane >> 2, tig = lane & 3;

    float o[16][4];
    gemm_mainloop<8, 16>(A, g_wfgT, CDIM, CDIM, m0, 0, t, w, gid, tig, o);

    const int r0 = m0 + w * 16 + gid;
    #pragma unroll
    for (int nt = 0; nt < 16; nt++) {
        const int cc = nt * 8 + 2 * tig;           // 0..127
        __nv_bfloat16* dst0;
        __nv_bfloat16* dst1;
        float b0, b1;
        if (nt < 8) {
            b0 = bf[cc]; b1 = bf[cc + 1];
            dst0 = &g_fb[(size_t)r0 * DDIM + cc];
            dst1 = &g_fb[(size_t)(r0 + 8) * DDIM + cc];
        } else {
            b0 = bg[cc - 64]; b1 = bg[cc - 63];
            dst0 = &g_gb[(size_t)r0 * DDIM + cc - 64];
            dst1 = &g_gb[(size_t)(r0 + 8) * DDIM + cc - 64];
        }
        __nv_bfloat162 v0 = __floats2bfloat162_rn(o[nt][0] + b0, o[nt][1] + b1);
        __nv_bfloat162 v1 = __floats2bfloat162_rn(o[nt][2] + b0, o[nt][3] + b1);
        *(__nv_bfloat162*)dst0 = v0;
        *(__nv_bfloat162*)dst1 = v1;
    }
}

// ---------------------------------------------------------------------------
// proj_big: h projection, BN=64, transposed bf16 store (round-8 proven)
// ---------------------------------------------------------------------------
#define TSTR 136
__global__ void __launch_bounds__(256)
proj_big(const __nv_bfloat16* __restrict__ A, const float* __restrict__ bias)
{
    const int m0 = blockIdx.x * 128;
    const int n0 = blockIdx.y * 64;
    const int t = threadIdx.x, w = t >> 5, lane = t & 31;
    const int gid = lane >> 2, tig = lane & 3;

    float o[8][4];
    gemm_mainloop<8, 8>(A, g_whT, CDIM, CDIM, m0, n0, t, w, gid, tig, o);

    __nv_bfloat16* st = (__nv_bfloat16*)psm;
    __syncthreads();
    const int m = w * 16 + gid;
    #pragma unroll
    for (int nt = 0; nt < 8; nt++) {
        const int cc = nt * 8 + 2 * tig;
        const float b0 = bias[n0 + cc], b1 = bias[n0 + cc + 1];
        st[cc * TSTR + m]           = __float2bfloat16(o[nt][0] + b0);
        st[(cc + 1) * TSTR + m]     = __float2bfloat16(o[nt][1] + b1);
        st[cc * TSTR + m + 8]       = __float2bfloat16(o[nt][2] + b0);
        st[(cc + 1) * TSTR + m + 8] = __float2bfloat16(o[nt][3] + b1);
    }
    __syncthreads();

    const int b  = m0 >> 12;
    const int nb = m0 & 4095;
    #pragma unroll
    for (int r = 0; r < 4; r++) {
        int idx = t + 256 * r;
        int row = idx >> 4, seg = idx & 15;
        float4 v = *(const float4*)&st[row * TSTR + seg * 8];
        *(float4*)&g_hTb[((size_t)b * CDIM + n0 + row) * SEQ + nb + seg * 8] = v;
    }
}

// ---------------------------------------------------------------------------
// skernel: P[b][q][k] = exp(f_q . g_k) + partial row sums (round-8 proven)
// ---------------------------------------------------------------------------
__global__ void __launch_bounds__(256)
skernel()
{
    __shared__ __nv_bfloat16 sf[128 * PSTR];
    __shared__ __nv_bfloat16 sg[128 * PSTR];

    const int qb = blockIdx.x, kb = blockIdx.y, b = blockIdx.z;
    const int q0 = qb * 128, k0 = kb * 128;
    const int t = threadIdx.x, w = t >> 5, lane = t & 31;
    const int gid = lane >> 2, tig = lane & 3;

    const __nv_bfloat16* fptr = g_fb + (size_t)(b * SEQ + q0) * DDIM;
    const __nv_bfloat16* gptr = g_gb + (size_t)(b * SEQ + k0) * DDIM;
    #pragma unroll
    for (int r = 0; r < 4; r++) {
        int idx = t + 256 * r;
        int row = idx >> 3, ck = idx & 7;
        cp16(&sf[row * PSTR + ck * 8], fptr + (size_t)row * DDIM + ck * 8);
    }
    #pragma unroll
    for (int r = 0; r < 4; r++) {
        int idx = t + 256 * r;
        int row = idx >> 3, ck = idx & 7;
        cp16(&sg[row * PSTR + ck * 8], gptr + (size_t)row * DDIM + ck * 8);
    }
    cp_commit();
    asm volatile("cp.async.wait_group 0;\n");
    __syncthreads();

    u32 fa[4][4];
    {
        const __nv_bfloat16* frow = &sf[(w * 16 + gid) * PSTR];
        #pragma unroll
        for (int ks = 0; ks < 4; ks++) {
            fa[ks][0] = *(const u32*)&frow[ks * 16 + 2 * tig];
            fa[ks][1] = *(const u32*)&frow[8 * PSTR + ks * 16 + 2 * tig];
            fa[ks][2] = *(const u32*)&frow[ks * 16 + 2 * tig + 8];
            fa[ks][3] = *(const u32*)&frow[8 * PSTR + ks * 16 + 2 * tig + 8];
        }
    }

    float s[16][4];
    #pragma unroll
    for (int nt = 0; nt < 16; nt++)
        #pragma unroll
        for (int j = 0; j < 4; j++) s[nt][j] = 0.f;

    #pragma unroll
    for (int nt = 0; nt < 16; nt++) {
        const __nv_bfloat16* brow = &sg[(nt * 8 + gid) * PSTR + 2 * tig];
        #pragma unroll
        for (int ks = 0; ks < 4; ks++) {
            u32 b0 = *(const u32*)&brow[ks * 16];
            u32 b1 = *(const u32*)&brow[ks * 16 + 8];
            mma16816(s[nt], fa[ks], b0, b1);
        }
    }

    __nv_bfloat16* P = g_pb + (size_t)b * SEQ * SEQ;
    const int row0 = q0 + w * 16 + gid;
    const int row1 = row0 + 8;
    float sl0 = 0.f, sl1 = 0.f;
    #pragma unroll
    for (int nt = 0; nt < 16; nt++) {
        float p0 = __expf(s[nt][0]);
        float p1 = __expf(s[nt][1]);
        float p2 = __expf(s[nt][2]);
        float p3 = __expf(s[nt][3]);
        sl0 += p0 + p1;
        sl1 += p2 + p3;
        const int key = k0 + nt * 8 + 2 * tig;
        __nv_bfloat162 lo = __floats2bfloat162_rn(p0, p1);
        __nv_bfloat162 hi = __floats2bfloat162_rn(p2, p3);
        *(__nv_bfloat162*)&P[(size_t)row0 * SEQ + key] = lo;
        *(__nv_bfloat162*)&P[(size_t)row1 * SEQ + key] = hi;
    }
    sl0 += __shfl_xor_sync(0xffffffffu, sl0, 1);
    sl0 += __shfl_xor_sync(0xffffffffu, sl0, 2);
    sl1 += __shfl_xor_sync(0xffffffffu, sl1, 1);
    sl1 += __shfl_xor_sync(0xffffffffu, sl1, 2);
    if (tig == 0) {
        g_lpart[kb * MROWS + b * SEQ + row0] = sl0;
        g_lpart[kb * MROWS + b * SEQ + row1] = sl1;
    }
}

__global__ void __launch_bounds__(256)
reduce_l()
{
    const int m = blockIdx.x * 256 + threadIdx.x;
    float s = 0.f;
    #pragma unroll
    for (int kb = 0; kb < NKB; kb++) s += g_lpart[kb * MROWS + m];
    g_l[m] = s;
}

// ---------------------------------------------------------------------------
// pvkernel: out = x + (gamma/l[row]) * (P . h^T). BN=128.
// ---------------------------------------------------------------------------
__global__ void __launch_bounds__(256)
pvkernel(const float* __restrict__ x, const float* __restrict__ gamma_p,
         float* __restrict__ out)
{
    const int n0 = blockIdx.x * 128;    // channel block (x-major for P L2 reuse)
    const int m0 = blockIdx.y * 128;    // global row block
    const int b  = m0 >> 12;
    const int t = threadIdx.x, w = t >> 5, lane = t & 31;
    const int gid = lane >> 2, tig = lane & 3;

    const __nv_bfloat16* Pq = g_pb + ((size_t)b * SEQ + (m0 & 4095)) * SEQ;
    const __nv_bfloat16* BT = g_hTb + (size_t)b * CDIM * SEQ;

    float o[16][4];
    gemm_mainloop<SEQ / 64, 16>(Pq, BT, SEQ, SEQ, 0, n0, t, w, gid, tig, o);

    const float gamma = *gamma_p;
    const int r0 = m0 + w * 16 + gid;
    const int r1 = r0 + 8;
    const float sc0 = gamma / g_l[r0];
    const float sc1 = gamma / g_l[r1];
    #pragma unroll
    for (int nt = 0; nt < 16; nt++) {
        const int cc = n0 + nt * 8 + 2 * tig;
        float2 x0 = *(const float2*)&x[(size_t)r0 * CDIM + cc];
        float2 x1 = *(const float2*)&x[(size_t)r1 * CDIM + cc];
        float2 o0, o1;
        o0.x = fmaf(o[nt][0], sc0, x0.x);
        o0.y = fmaf(o[nt][1], sc0, x0.y);
        o1.x = fmaf(o[nt][2], sc1, x1.x);
        o1.y = fmaf(o[nt][3], sc1, x1.y);
        *(float2*)&out[(size_t)r0 * CDIM + cc] = o0;
        *(float2*)&out[(size_t)r1 * CDIM + cc] = o1;
    }
}

// ---------------------------------------------------------------------------
extern "C" void kernel_launch(void* const* d_in, const int* in_sizes, int n_in,
                              void* d_out, int out_size)
{
    const float* x     = (const float*)d_in[0];
    const float* Wf    = (const float*)d_in[1];
    const float* bf    = (const float*)d_in[2];
    const float* Wg    = (const float*)d_in[3];
    const float* bg    = (const float*)d_in[4];
    const float* Wh    = (const float*)d_in[5];
    const float* bh    = (const float*)d_in[6];
    const float* gamma = (const float*)d_in[7];
    float* out = (float*)d_out;

    __nv_bfloat16* xb;
    cudaGetSymbolAddress((void**)&xb, g_xb);

    static cudaStream_t s1 = nullptr;
    static cudaEvent_t  e0 = nullptr, e1 = nullptr;
    if (!s1) {
        cudaStreamCreateWithFlags(&s1, cudaStreamNonBlocking);
        cudaEventCreateWithFlags(&e0, cudaEventDisableTiming);
        cudaEventCreateWithFlags(&e1, cudaEventDisableTiming);
        cudaFuncSetAttribute(proj_fg,
                             cudaFuncAttributeMaxDynamicSharedMemorySize, SMEM_N16);
        cudaFuncSetAttribute(proj_big,
                             cudaFuncAttributeMaxDynamicSharedMemorySize, SMEM_N8);
        cudaFuncSetAttribute(pvkernel,
                             cudaFuncAttributeMaxDynamicSharedMemorySize, SMEM_N16);
    }

    // default stream: casts, then fork
    cast_x <<<MROWS * CDIM / 4 / 256, 256>>>(x, xb);
    cast_w3<<<(65536 + CDIM * CDIM) / 256, 256>>>(Wf, Wg, Wh);
    cudaEventRecord(e0, 0);

    // side stream: f+g projection -> S/P/exp -> l reduction
    cudaStreamWaitEvent(s1, e0, 0);
    proj_fg <<<dim3(MROWS / 128), 256, SMEM_N16, s1>>>(xb, bf, bg);
    skernel <<<dim3(SEQ / 128, SEQ / 128, BATCH), 256, 0, s1>>>();
    reduce_l<<<MROWS / 256, 256, 0, s1>>>();
    cudaEventRecord(e1, s1);

    // default stream: h projection overlaps the side stream
    proj_big<<<dim3(MROWS / 128, CDIM / 64), 256, SMEM_N8>>>(xb, bh);

    // join, then PV
    cudaStreamWaitEvent(0, e1, 0);
    pvkernel<<<dim3(CDIM / 128, MROWS / 128), 256, SMEM_N16>>>(x, gamma, out);
}